// round 13
// baseline (speedup 1.0000x reference)
#include <cuda_runtime.h>
#include <cuda_bf16.h>
#include <cstdint>

static constexpr int BATCH = 2048;   // B
static constexpr int NODES = 128;    // M
static constexpr int DIM   = 512;    // D == H
static constexpr int KX    = 2048;   // packed X cols: [img_mean|txt_mean|it|ii]

// k_main grid partition (order matters: producers before consumers)
static constexpr int N1_WCOMB = 128;                    // [0,128)
static constexpr int N1_PASS  = 32;                     // [128,160)
static constexpr int N1_BCOMB = 2;                      // [160,162)
static constexpr int N1_WPACK = 64;                     // [162,226)
static constexpr int N1_P2    = 128;                    // [226,354)  gemm K[1024,2048)
static constexpr int N1_MEAN  = 512;                    // [354,866)
static constexpr int GRID1 = N1_WCOMB + N1_PASS + N1_BCOMB + N1_WPACK + N1_P2 + N1_MEAN;

static constexpr int N_TAIL = 128;                      // k_tail CTAs (8 x 16)

// per-stage SMEM block: Ahi 8K | Alo 8K | Bhi 4K | Blo 4K
static constexpr int STG = 24576;

// Scratch (static __device__ globals — allocation-free)
__device__ __nv_bfloat16 g_Xhi[(size_t)BATCH * KX];
__device__ __nv_bfloat16 g_Xlo[(size_t)BATCH * KX];
__device__ __nv_bfloat16 g_Whi[(size_t)DIM * KX];
__device__ __nv_bfloat16 g_Wlo[(size_t)DIM * KX];
__device__ float g_bcomb[DIM];
// sync state (zero-init at load; self-reset by the last k_tail CTA each run)
__device__ uint32_t g_c_wcomb;
__device__ uint32_t g_c_pass;
__device__ uint32_t g_done;

// ---------------------------------------------------------------------------
// helpers
// ---------------------------------------------------------------------------
__device__ __forceinline__ void split_store4(__nv_bfloat16* hiP, __nv_bfloat16* loP,
                                             size_t idx, float4 v)
{
    union U { __nv_bfloat16 b[4]; uint2 u; } hu, lu;
    float f[4] = {v.x, v.y, v.z, v.w};
    #pragma unroll
    for (int i = 0; i < 4; ++i) {
        __nv_bfloat16 h = __float2bfloat16(f[i]);
        hu.b[i] = h;
        lu.b[i] = __float2bfloat16(f[i] - __bfloat162float(h));
    }
    *reinterpret_cast<uint2*>(hiP + idx) = hu.u;
    *reinterpret_cast<uint2*>(loP + idx) = lu.u;
}

__device__ __forceinline__ uint32_t sw_off(int r, int c) {
    return (uint32_t)(r * 64 + ((c ^ ((r >> 1) & 3)) << 4));
}

__device__ __forceinline__ void cp_async16(uint32_t dst, const void* src) {
    asm volatile("cp.async.cg.shared.global [%0], [%1], 16;\n" :: "r"(dst), "l"(src));
}
__device__ __forceinline__ void cp_commit() { asm volatile("cp.async.commit_group;\n"); }
template<int N>
__device__ __forceinline__ void cp_wait() {
    asm volatile("cp.async.wait_group %0;\n" :: "n"(N));
}

__device__ __forceinline__ void ldsm4(uint32_t* r, uint32_t addr) {
    asm volatile("ldmatrix.sync.aligned.m8n8.x4.shared.b16 {%0,%1,%2,%3}, [%4];\n"
                 : "=r"(r[0]), "=r"(r[1]), "=r"(r[2]), "=r"(r[3]) : "r"(addr));
}
__device__ __forceinline__ void mma16816(float* c, const uint32_t* a, const uint32_t* b) {
    asm volatile("mma.sync.aligned.m16n8k16.row.col.f32.bf16.bf16.f32 "
                 "{%0,%1,%2,%3}, {%4,%5,%6,%7}, {%8,%9}, {%0,%1,%2,%3};\n"
                 : "+f"(c[0]), "+f"(c[1]), "+f"(c[2]), "+f"(c[3])
                 : "r"(a[0]), "r"(a[1]), "r"(a[2]), "r"(a[3]), "r"(b[0]), "r"(b[1]));
}

__device__ __forceinline__ uint32_t ld_acq(const uint32_t* p) {
    uint32_t v;
    asm volatile("ld.acquire.gpu.global.u32 %0, [%1];" : "=r"(v) : "l"(p) : "memory");
    return v;
}
__device__ __forceinline__ void publish(uint32_t* c) {
    __threadfence();
    __syncthreads();
    if (threadIdx.x == 0) atomicAdd(c, 1u);
}
__device__ __forceinline__ void wait_ge(const uint32_t* c, uint32_t tgt) {
    while (ld_acq(c) < tgt) __nanosleep(256);
}

// ---------------------------------------------------------------------------
// GEMM tile body, templated pipeline depth. CTA 128(M) x 64(N), KBLK=32,
// 8 warps. NS contiguous 24KB smem stages. 32 KBLK iters from `kbase`.
// fin=false: store raw partial. fin=true: += partial from out, bias, relu.
// ---------------------------------------------------------------------------
template<int NS>
__device__ __forceinline__ void gemm_tile(float* __restrict__ out, unsigned char* smp,
                                          int m0, int n0, int kbase, bool fin)
{
    const uint32_t smBase = (uint32_t)__cvta_generic_to_shared(smp);

    const int tid = threadIdx.x;
    const int l   = tid & 31;
    const int wid = tid >> 5;
    const int wm  = wid >> 1;
    const int wn  = wid & 1;

    uint32_t offA[2][2], offB[2][2];
    {
        const int ti = l >> 3;
        #pragma unroll
        for (int f = 0; f < 2; ++f)
            #pragma unroll
            for (int ks = 0; ks < 2; ++ks) {
                int tm = wm * 32 + f * 16 + (ti & 1) * 8 + (l & 7);
                int tc = ks * 2 + (ti >> 1);
                offA[f][ks] = (uint32_t)(tm * 64 + ((tc ^ ((tm >> 1) & 3)) << 4));
            }
        #pragma unroll
        for (int q = 0; q < 2; ++q)
            #pragma unroll
            for (int ks = 0; ks < 2; ++ks) {
                int tn = wn * 32 + q * 16 + (ti >> 1) * 8 + (l & 7);
                int tc = ks * 2 + (ti & 1);
                offB[q][ks] = (uint32_t)(tn * 64 + ((tc ^ ((tn >> 1) & 3)) << 4));
            }
    }

    const int ar0 = tid >> 2,         ac0 = tid & 3;
    const int ar1 = (tid + 256) >> 2, ac1 = tid & 3;
    const int br  = tid >> 2,         bcc = tid & 3;

    auto load_stage = [&](int s, int kb) {
        const uint32_t base = smBase + s * STG;
        const uint32_t aHi = base, aLo = base + 8192;
        const uint32_t bHi = base + 16384, bLo = base + 20480;
        cp_async16(aHi + sw_off(ar0, ac0), g_Xhi + (size_t)(m0 + ar0) * KX + kb + ac0 * 8);
        cp_async16(aLo + sw_off(ar0, ac0), g_Xlo + (size_t)(m0 + ar0) * KX + kb + ac0 * 8);
        cp_async16(aHi + sw_off(ar1, ac1), g_Xhi + (size_t)(m0 + ar1) * KX + kb + ac1 * 8);
        cp_async16(aLo + sw_off(ar1, ac1), g_Xlo + (size_t)(m0 + ar1) * KX + kb + ac1 * 8);
        cp_async16(bHi + sw_off(br, bcc),  g_Whi + (size_t)(n0 + br) * KX + kb + bcc * 8);
        cp_async16(bLo + sw_off(br, bcc),  g_Wlo + (size_t)(n0 + br) * KX + kb + bcc * 8);
    };

    float acc[2][4][4] = {};

    #pragma unroll
    for (int s = 0; s < NS - 1; ++s) {
        load_stage(s, kbase + s * 32);
        cp_commit();
    }

    const int NIT = 32;
    for (int it = 0; it < NIT; ++it) {
        if (it + NS - 1 < NIT) load_stage((it + NS - 1) % NS, kbase + (it + NS - 1) * 32);
        cp_commit();
        cp_wait<NS - 1>();
        __syncthreads();

        const uint32_t base = smBase + (it % NS) * STG;
        const uint32_t aHi = base, aLo = base + 8192;
        const uint32_t bHi = base + 16384, bLo = base + 20480;

        #pragma unroll
        for (int ks = 0; ks < 2; ++ks) {
            uint32_t ahi[2][4], alo[2][4], bhi[2][4], blo[2][4];
            ldsm4(ahi[0], aHi + offA[0][ks]);
            ldsm4(ahi[1], aHi + offA[1][ks]);
            ldsm4(alo[0], aLo + offA[0][ks]);
            ldsm4(alo[1], aLo + offA[1][ks]);
            ldsm4(bhi[0], bHi + offB[0][ks]);
            ldsm4(bhi[1], bHi + offB[1][ks]);
            ldsm4(blo[0], bLo + offB[0][ks]);
            ldsm4(blo[1], bLo + offB[1][ks]);

            #pragma unroll
            for (int mf = 0; mf < 2; ++mf)
                #pragma unroll
                for (int nf = 0; nf < 4; ++nf) {
                    const uint32_t* bh = &bhi[nf >> 1][(nf & 1) * 2];
                    const uint32_t* bl = &blo[nf >> 1][(nf & 1) * 2];
                    mma16816(acc[mf][nf], ahi[mf], bh);   // hi*hi
                    mma16816(acc[mf][nf], ahi[mf], bl);   // hi*lo
                    mma16816(acc[mf][nf], alo[mf], bh);   // lo*hi
                }
        }
        __syncthreads();       // protects slot reuse by the load NS-1 ahead
    }

    #pragma unroll
    for (int mf = 0; mf < 2; ++mf) {
        const int m = m0 + wm * 32 + mf * 16 + (l >> 2);
        #pragma unroll
        for (int nf = 0; nf < 4; ++nf) {
            const int n = n0 + wn * 32 + nf * 8 + (l & 3) * 2;
            float* p0 = out + (size_t)m * DIM + n;
            float* p1 = out + (size_t)(m + 8) * DIM + n;
            if (fin) {
                const float2 bb = *reinterpret_cast<const float2*>(g_bcomb + n);
                const float2 q0 = *reinterpret_cast<const float2*>(p0);
                const float2 q1 = *reinterpret_cast<const float2*>(p1);
                float2 o0, o1;
                o0.x = fmaxf(acc[mf][nf][0] + q0.x + bb.x, 0.f);
                o0.y = fmaxf(acc[mf][nf][1] + q0.y + bb.y, 0.f);
                o1.x = fmaxf(acc[mf][nf][2] + q1.x + bb.x, 0.f);
                o1.y = fmaxf(acc[mf][nf][3] + q1.y + bb.y, 0.f);
                *reinterpret_cast<float2*>(p0) = o0;
                *reinterpret_cast<float2*>(p1) = o1;
            } else {
                *reinterpret_cast<float2*>(p0) = make_float2(acc[mf][nf][0], acc[mf][nf][1]);
                *reinterpret_cast<float2*>(p1) = make_float2(acc[mf][nf][2], acc[mf][nf][3]);
            }
        }
    }
}

// ---------------------------------------------------------------------------
// Kernel 1 (k_main): weight prep + passthrough pack + GEMM part-2 (overlapped)
// + mean stream. Static 48KB smem (2-stage gemm path).
// ---------------------------------------------------------------------------
__global__ void __launch_bounds__(256) k_main(
    const float* __restrict__ itex, const float* __restrict__ iimg,
    const float* __restrict__ btxt, const float* __restrict__ bimg,
    const float* __restrict__ Wri,  const float* __restrict__ Wrt,
    const float* __restrict__ Wu,   const float* __restrict__ bu,
    const float* __restrict__ bli,  const float* __restrict__ blt,
    const float* __restrict__ Wli,  const float* __restrict__ Wlt,
    float* __restrict__ out)
{
    __shared__ __align__(1024) unsigned char smu[2 * STG];

    const int bx  = blockIdx.x;
    const int tid = threadIdx.x;

    if (bx < N1_WCOMB) {
        // ---- W_comb tile -> bf16 hi/lo into g_W cols [1024,2048) ----
        float (*As)[68] = reinterpret_cast<float(*)[68]>(smu);
        float (*Bs)[64] = reinterpret_cast<float(*)[64]>(smu + 16384);

        const int n0 = (bx & 15) * 64;
        const int m0 = (bx >> 4) * 64;
        const int tx = tid & 15, ty = tid >> 4;
        const int arow = tid >> 2, ac = (tid & 3) * 4;
        const int brow = tid >> 4, bc = (tid & 15) * 4;

        float acc[4][4] = {};
        float4 ra, rb;
        {
            float4 x = *reinterpret_cast<const float4*>(Wri + (m0 + arow) * 512 + ac);
            float4 y = *reinterpret_cast<const float4*>(Wrt + (m0 + arow) * 512 + ac);
            ra = make_float4(x.x + y.x, x.y + y.y, x.z + y.z, x.w + y.w);
            rb = *reinterpret_cast<const float4*>(Wu + brow * 1024 + n0 + bc);
        }
        for (int kt = 0; kt < 32; ++kt) {
            As[ac + 0][arow] = ra.x; As[ac + 1][arow] = ra.y;
            As[ac + 2][arow] = ra.z; As[ac + 3][arow] = ra.w;
            *reinterpret_cast<float4*>(&Bs[brow][bc]) = rb;
            __syncthreads();
            if (kt < 31) {
                const int h0 = (kt + 1) * 16;
                float4 x = *reinterpret_cast<const float4*>(Wri + (m0 + arow) * 512 + h0 + ac);
                float4 y = *reinterpret_cast<const float4*>(Wrt + (m0 + arow) * 512 + h0 + ac);
                ra = make_float4(x.x + y.x, x.y + y.y, x.z + y.z, x.w + y.w);
                rb = *reinterpret_cast<const float4*>(Wu + (h0 + brow) * 1024 + n0 + bc);
            }
            #pragma unroll
            for (int kk = 0; kk < 16; ++kk) {
                float4 a = *reinterpret_cast<const float4*>(&As[kk][ty * 4]);
                float4 b = *reinterpret_cast<const float4*>(&Bs[kk][tx * 4]);
                acc[0][0] += a.x*b.x; acc[0][1] += a.x*b.y; acc[0][2] += a.x*b.z; acc[0][3] += a.x*b.w;
                acc[1][0] += a.y*b.x; acc[1][1] += a.y*b.y; acc[1][2] += a.y*b.z; acc[1][3] += a.y*b.w;
                acc[2][0] += a.z*b.x; acc[2][1] += a.z*b.y; acc[2][2] += a.z*b.z; acc[2][3] += a.z*b.w;
                acc[3][0] += a.w*b.x; acc[3][1] += a.w*b.y; acc[3][2] += a.w*b.z; acc[3][3] += a.w*b.w;
            }
            __syncthreads();
        }
        #pragma unroll
        for (int rr = 0; rr < 4; ++rr) {
            float4 o = make_float4(acc[rr][0], acc[rr][1], acc[rr][2], acc[rr][3]);
            split_store4(g_Whi, g_Wlo,
                         (size_t)(m0 + ty * 4 + rr) * KX + 1024 + n0 + tx * 4, o);
        }
        publish(&g_c_wcomb);
        return;
    }

    if (bx < N1_WCOMB + N1_PASS) {
        // ---- passthrough pack: X cols [1024,2048) from it/ii, 64 rows/CTA ----
        const int j = bx - N1_WCOMB;
        #pragma unroll 4
        for (int q = 0; q < 64; ++q) {
            const int id = q * 256 + tid;
            const int r  = id >> 8;
            const int ci = id & 255;
            const int b  = j * 64 + r;
            float4 v;
            int xcol;
            if (ci < 128) { v = reinterpret_cast<const float4*>(itex + (size_t)b * DIM)[ci];
                            xcol = 1024 + ci * 4; }
            else          { v = reinterpret_cast<const float4*>(iimg + (size_t)b * DIM)[ci - 128];
                            xcol = 1536 + (ci - 128) * 4; }
            split_store4(g_Xhi, g_Xlo, (size_t)b * KX + xcol, v);
        }
        publish(&g_c_pass);
        return;
    }

    if (bx < N1_WCOMB + N1_PASS + N1_BCOMB) {
        // ---- b_comb ----
        float* bs = reinterpret_cast<float*>(smu);
        bs[tid] = bu[tid];
        bs[tid + 256] = bu[tid + 256];
        __syncthreads();
        const int n = (bx - N1_WCOMB - N1_PASS) * 256 + tid;
        const float4* p1 = reinterpret_cast<const float4*>(Wri + n * 512);
        const float4* p2 = reinterpret_cast<const float4*>(Wrt + n * 512);
        float acc = 0.f;
        #pragma unroll 4
        for (int h4 = 0; h4 < 128; ++h4) {
            float4 a = p1[h4], b = p2[h4];
            const float* bb = bs + h4 * 4;
            acc += (a.x + b.x) * bb[0] + (a.y + b.y) * bb[1]
                 + (a.z + b.z) * bb[2] + (a.w + b.w) * bb[3];
        }
        g_bcomb[n] = acc + bli[n] + blt[n];
        return;
    }

    if (bx < N1_WCOMB + N1_PASS + N1_BCOMB + N1_WPACK) {
        // ---- pack [Wli | Wlt] -> g_W cols [0,1024) ----
        const int base = (bx - N1_WCOMB - N1_PASS - N1_BCOMB) * 256 * 8;
        #pragma unroll
        for (int it = 0; it < 8; ++it) {
            const int id = base + it * 256 + tid;
            const int n  = id >> 8;
            const int k  = (id & 255) * 4;
            float4 v;
            if (k < 512) v = *reinterpret_cast<const float4*>(Wli + n * 512 + k);
            else         v = *reinterpret_cast<const float4*>(Wlt + n * 512 + (k - 512));
            split_store4(g_Whi, g_Wlo, (size_t)n * KX + k, v);
        }
        return;
    }

    if (bx < N1_WCOMB + N1_PASS + N1_BCOMB + N1_WPACK + N1_P2) {
        // ---- GEMM part-2: K [1024,2048), overlapped with the mean stream ----
        if (tid == 0) {
            wait_ge(&g_c_wcomb, N1_WCOMB);
            wait_ge(&g_c_pass,  N1_PASS);
        }
        __syncthreads();
        const int id = bx - (N1_WCOMB + N1_PASS + N1_BCOMB + N1_WPACK);
        const int n0 = (id & 7) * 64;
        const int m0 = (id >> 3) * 128;
        gemm_tile<2>(out, smu, m0, n0, 1024, false);
        return;
    }

    // ---- mean stream: 4 contiguous batch rows per CTA, cols [0,1024) ----
    {
        const int widx = bx - (N1_WCOMB + N1_PASS + N1_BCOMB + N1_WPACK + N1_P2);
        const bool lo  = (tid < 128);
        const int chunk = lo ? tid : (tid - 128);
        const int xoff  = lo ? 0 : 512;
        const float* srcM = lo ? bimg : btxt;
        const float s = 1.0f / (float)NODES;

        #pragma unroll 1
        for (int r = 0; r < 4; ++r) {
            const int b = widx * 4 + r;
            const float4* p = reinterpret_cast<const float4*>(
                                  srcM + (size_t)b * NODES * DIM) + chunk;
            float4 acc = make_float4(0.f, 0.f, 0.f, 0.f);
            #pragma unroll 16
            for (int m = 0; m < NODES; ++m) {
                float4 v = __ldcs(p + (size_t)m * (DIM / 4));
                acc.x += v.x; acc.y += v.y; acc.z += v.z; acc.w += v.w;
            }
            acc.x *= s; acc.y *= s; acc.z *= s; acc.w *= s;
            split_store4(g_Xhi, g_Xlo, (size_t)b * KX + xoff + chunk * 4, acc);
        }
    }
}

// ---------------------------------------------------------------------------
// Kernel 2 (k_tail): GEMM part-1 (K [0,1024)) + finalize. 4-stage pipeline
// (96KB dynamic smem) to hide DRAM latency (stream evicted X/W from L2).
// Last CTA self-resets sync flags for the next graph replay.
// ---------------------------------------------------------------------------
__global__ void __launch_bounds__(256) k_tail(float* __restrict__ out)
{
    extern __shared__ __align__(1024) unsigned char smd[];
    const int n0 = blockIdx.x * 64;
    const int m0 = blockIdx.y * 128;
    gemm_tile<4>(out, smd, m0, n0, 0, true);

    __syncthreads();
    if (threadIdx.x == 0) {
        const uint32_t old = atomicAdd(&g_done, 1u);
        if (old == (uint32_t)(N_TAIL - 1)) {
            g_c_wcomb = 0;
            g_c_pass  = 0;
            g_done    = 0;
            __threadfence();
        }
    }
}

// ---------------------------------------------------------------------------
extern "C" void kernel_launch(void* const* d_in, const int* in_sizes, int n_in,
                              void* d_out, int out_size)
{
    const float* input_text = (const float*)d_in[0];
    const float* input_img  = (const float*)d_in[1];
    const float* btxt       = (const float*)d_in[2];
    const float* bimg       = (const float*)d_in[3];
    const float* W_user     = (const float*)d_in[4];
    const float* b_user     = (const float*)d_in[5];
    const float* W_l_img    = (const float*)d_in[6];
    const float* b_l_img    = (const float*)d_in[7];
    const float* W_r_img    = (const float*)d_in[8];
    const float* W_l_txt    = (const float*)d_in[9];
    const float* b_l_txt    = (const float*)d_in[10];
    const float* W_r_txt    = (const float*)d_in[11];
    float* out = (float*)d_out;

    cudaFuncSetAttribute(k_tail, cudaFuncAttributeMaxDynamicSharedMemorySize, 4 * STG);

    k_main<<<GRID1, 256>>>(input_text, input_img, btxt, bimg,
                           W_r_img, W_r_txt, W_user, b_user, b_l_img, b_l_txt,
                           W_l_img, W_l_txt, out);
    k_tail<<<dim3(8, 16), 256, 4 * STG>>>(out);
}

// round 14
// speedup vs baseline: 1.1241x; 1.1241x over previous
#include <cuda_runtime.h>
#include <cuda_bf16.h>
#include <cstdint>

static constexpr int BATCH = 2048;   // B
static constexpr int NODES = 128;    // M
static constexpr int DIM   = 512;    // D == H
static constexpr int KX    = 2048;   // packed X cols: [img_mean|txt_mean|it|ii]

// k_main grid partition (order matters: producers before consumers)
static constexpr int N1_WCOMB = 128;                    // [0,128)
static constexpr int N1_PASS  = 32;                     // [128,160)
static constexpr int N1_BCOMB = 2;                      // [160,162)
static constexpr int N1_WPACK = 64;                     // [162,226)
static constexpr int N1_P2    = 128;                    // [226,354)  gemm K[1024,2048)
static constexpr int N1_MEAN  = 512;                    // [354,866)
static constexpr int GRID1 = N1_WCOMB + N1_PASS + N1_BCOMB + N1_WPACK + N1_P2 + N1_MEAN;

static constexpr int N_TAIL = 128;                      // k_tail CTAs (8 x 16)

// Scratch (static __device__ globals — allocation-free)
__device__ __nv_bfloat16 g_Xhi[(size_t)BATCH * KX];
__device__ __nv_bfloat16 g_Xlo[(size_t)BATCH * KX];
__device__ __nv_bfloat16 g_Whi[(size_t)DIM * KX];
__device__ __nv_bfloat16 g_Wlo[(size_t)DIM * KX];
__device__ float g_bcomb[DIM];
// sync state (zero-init at load; self-reset by the last k_tail CTA each run)
__device__ uint32_t g_c_wcomb;
__device__ uint32_t g_c_pass;
__device__ uint32_t g_done;

// ---------------------------------------------------------------------------
// helpers
// ---------------------------------------------------------------------------
__device__ __forceinline__ void split_store4(__nv_bfloat16* hiP, __nv_bfloat16* loP,
                                             size_t idx, float4 v)
{
    union U { __nv_bfloat16 b[4]; uint2 u; } hu, lu;
    float f[4] = {v.x, v.y, v.z, v.w};
    #pragma unroll
    for (int i = 0; i < 4; ++i) {
        __nv_bfloat16 h = __float2bfloat16(f[i]);
        hu.b[i] = h;
        lu.b[i] = __float2bfloat16(f[i] - __bfloat162float(h));
    }
    *reinterpret_cast<uint2*>(hiP + idx) = hu.u;
    *reinterpret_cast<uint2*>(loP + idx) = lu.u;
}

__device__ __forceinline__ uint32_t sw_off(int r, int c) {
    return (uint32_t)(r * 64 + ((c ^ ((r >> 1) & 3)) << 4));
}

__device__ __forceinline__ void cp_async16(uint32_t dst, const void* src) {
    asm volatile("cp.async.cg.shared.global [%0], [%1], 16;\n" :: "r"(dst), "l"(src));
}
__device__ __forceinline__ void cp_commit() { asm volatile("cp.async.commit_group;\n"); }
__device__ __forceinline__ void cp_wait1()  { asm volatile("cp.async.wait_group 1;\n"); }

__device__ __forceinline__ void ldsm4(uint32_t* r, uint32_t addr) {
    asm volatile("ldmatrix.sync.aligned.m8n8.x4.shared.b16 {%0,%1,%2,%3}, [%4];\n"
                 : "=r"(r[0]), "=r"(r[1]), "=r"(r[2]), "=r"(r[3]) : "r"(addr));
}
__device__ __forceinline__ void mma16816(float* c, const uint32_t* a, const uint32_t* b) {
    asm volatile("mma.sync.aligned.m16n8k16.row.col.f32.bf16.bf16.f32 "
                 "{%0,%1,%2,%3}, {%4,%5,%6,%7}, {%8,%9}, {%0,%1,%2,%3};\n"
                 : "+f"(c[0]), "+f"(c[1]), "+f"(c[2]), "+f"(c[3])
                 : "r"(a[0]), "r"(a[1]), "r"(a[2]), "r"(a[3]), "r"(b[0]), "r"(b[1]));
}

__device__ __forceinline__ uint32_t ld_acq(const uint32_t* p) {
    uint32_t v;
    asm volatile("ld.acquire.gpu.global.u32 %0, [%1];" : "=r"(v) : "l"(p) : "memory");
    return v;
}
__device__ __forceinline__ void publish(uint32_t* c) {
    __threadfence();
    __syncthreads();
    if (threadIdx.x == 0) atomicAdd(c, 1u);
}
__device__ __forceinline__ void wait_ge(const uint32_t* c, uint32_t tgt) {
    while (ld_acq(c) < tgt) __nanosleep(256);
}

// ---------------------------------------------------------------------------
// GEMM tile body: CTA 128(M) x 64(N), KBLK=32, 8 warps, 2-stage cp.async.
// 32 KBLK iters from column `kbase`. fin=false: store raw partial.
// fin=true: += partial from out, add bias, relu.
// PIPE=true: issue all 16 ldsm up front per iter (higher regs; k_tail only).
// ---------------------------------------------------------------------------
template<bool PIPE>
__device__ __forceinline__ void gemm_tile(float* __restrict__ out, unsigned char* smp,
                                          int m0, int n0, int kbase, bool fin)
{
    const uint32_t smBase = (uint32_t)__cvta_generic_to_shared(smp);
    const uint32_t A_HI = smBase, A_LO = smBase + 16384;
    const uint32_t B_HI = smBase + 32768, B_LO = smBase + 40960;

    const int tid = threadIdx.x;
    const int l   = tid & 31;
    const int wid = tid >> 5;
    const int wm  = wid >> 1;
    const int wn  = wid & 1;

    uint32_t offA[2][2], offB[2][2];
    {
        const int ti = l >> 3;
        #pragma unroll
        for (int f = 0; f < 2; ++f)
            #pragma unroll
            for (int ks = 0; ks < 2; ++ks) {
                int tm = wm * 32 + f * 16 + (ti & 1) * 8 + (l & 7);
                int tc = ks * 2 + (ti >> 1);
                offA[f][ks] = (uint32_t)(tm * 64 + ((tc ^ ((tm >> 1) & 3)) << 4));
            }
        #pragma unroll
        for (int q = 0; q < 2; ++q)
            #pragma unroll
            for (int ks = 0; ks < 2; ++ks) {
                int tn = wn * 32 + q * 16 + (ti >> 1) * 8 + (l & 7);
                int tc = ks * 2 + (ti & 1);
                offB[q][ks] = (uint32_t)(tn * 64 + ((tc ^ ((tn >> 1) & 3)) << 4));
            }
    }

    const int ar0 = tid >> 2,         ac0 = tid & 3;
    const int ar1 = (tid + 256) >> 2, ac1 = tid & 3;
    const int br  = tid >> 2,         bcc = tid & 3;

    auto load_stage = [&](int s, int kb) {
        const uint32_t aHi = A_HI + s * 8192, aLo = A_LO + s * 8192;
        const uint32_t bHi = B_HI + s * 4096, bLo = B_LO + s * 4096;
        cp_async16(aHi + sw_off(ar0, ac0), g_Xhi + (size_t)(m0 + ar0) * KX + kb + ac0 * 8);
        cp_async16(aLo + sw_off(ar0, ac0), g_Xlo + (size_t)(m0 + ar0) * KX + kb + ac0 * 8);
        cp_async16(aHi + sw_off(ar1, ac1), g_Xhi + (size_t)(m0 + ar1) * KX + kb + ac1 * 8);
        cp_async16(aLo + sw_off(ar1, ac1), g_Xlo + (size_t)(m0 + ar1) * KX + kb + ac1 * 8);
        cp_async16(bHi + sw_off(br, bcc),  g_Whi + (size_t)(n0 + br) * KX + kb + bcc * 8);
        cp_async16(bLo + sw_off(br, bcc),  g_Wlo + (size_t)(n0 + br) * KX + kb + bcc * 8);
    };

    float acc[2][4][4] = {};

    load_stage(0, kbase);
    cp_commit();

    const int NIT = 32;
    for (int it = 0; it < NIT; ++it) {
        if (it + 1 < NIT) load_stage((it + 1) & 1, kbase + (it + 1) * 32);
        cp_commit();
        cp_wait1();
        __syncthreads();

        const int s = it & 1;
        const uint32_t aHi = A_HI + s * 8192, aLo = A_LO + s * 8192;
        const uint32_t bHi = B_HI + s * 4096, bLo = B_LO + s * 4096;

        if (PIPE) {
            // all 16 ldsm issued up front, then 48 MMAs back-to-back
            uint32_t ahi[2][2][4], alo[2][2][4], bhi[2][2][4], blo[2][2][4];
            #pragma unroll
            for (int ks = 0; ks < 2; ++ks) {
                ldsm4(ahi[ks][0], aHi + offA[0][ks]);
                ldsm4(ahi[ks][1], aHi + offA[1][ks]);
                ldsm4(alo[ks][0], aLo + offA[0][ks]);
                ldsm4(alo[ks][1], aLo + offA[1][ks]);
                ldsm4(bhi[ks][0], bHi + offB[0][ks]);
                ldsm4(bhi[ks][1], bHi + offB[1][ks]);
                ldsm4(blo[ks][0], bLo + offB[0][ks]);
                ldsm4(blo[ks][1], bLo + offB[1][ks]);
            }
            #pragma unroll
            for (int ks = 0; ks < 2; ++ks)
                #pragma unroll
                for (int mf = 0; mf < 2; ++mf)
                    #pragma unroll
                    for (int nf = 0; nf < 4; ++nf) {
                        const uint32_t* bh = &bhi[ks][nf >> 1][(nf & 1) * 2];
                        const uint32_t* bl = &blo[ks][nf >> 1][(nf & 1) * 2];
                        mma16816(acc[mf][nf], ahi[ks][mf], bh);
                        mma16816(acc[mf][nf], ahi[ks][mf], bl);
                        mma16816(acc[mf][nf], alo[ks][mf], bh);
                    }
        } else {
            #pragma unroll
            for (int ks = 0; ks < 2; ++ks) {
                uint32_t ahi[2][4], alo[2][4], bhi[2][4], blo[2][4];
                ldsm4(ahi[0], aHi + offA[0][ks]);
                ldsm4(ahi[1], aHi + offA[1][ks]);
                ldsm4(alo[0], aLo + offA[0][ks]);
                ldsm4(alo[1], aLo + offA[1][ks]);
                ldsm4(bhi[0], bHi + offB[0][ks]);
                ldsm4(bhi[1], bHi + offB[1][ks]);
                ldsm4(blo[0], bLo + offB[0][ks]);
                ldsm4(blo[1], bLo + offB[1][ks]);

                #pragma unroll
                for (int mf = 0; mf < 2; ++mf)
                    #pragma unroll
                    for (int nf = 0; nf < 4; ++nf) {
                        const uint32_t* bh = &bhi[nf >> 1][(nf & 1) * 2];
                        const uint32_t* bl = &blo[nf >> 1][(nf & 1) * 2];
                        mma16816(acc[mf][nf], ahi[mf], bh);   // hi*hi
                        mma16816(acc[mf][nf], ahi[mf], bl);   // hi*lo
                        mma16816(acc[mf][nf], alo[mf], bh);   // lo*hi
                    }
            }
        }
        __syncthreads();
    }

    #pragma unroll
    for (int mf = 0; mf < 2; ++mf) {
        const int m = m0 + wm * 32 + mf * 16 + (l >> 2);
        #pragma unroll
        for (int nf = 0; nf < 4; ++nf) {
            const int n = n0 + wn * 32 + nf * 8 + (l & 3) * 2;
            float* p0 = out + (size_t)m * DIM + n;
            float* p1 = out + (size_t)(m + 8) * DIM + n;
            if (fin) {
                const float2 bb = *reinterpret_cast<const float2*>(g_bcomb + n);
                const float2 q0 = *reinterpret_cast<const float2*>(p0);
                const float2 q1 = *reinterpret_cast<const float2*>(p1);
                float2 o0, o1;
                o0.x = fmaxf(acc[mf][nf][0] + q0.x + bb.x, 0.f);
                o0.y = fmaxf(acc[mf][nf][1] + q0.y + bb.y, 0.f);
                o1.x = fmaxf(acc[mf][nf][2] + q1.x + bb.x, 0.f);
                o1.y = fmaxf(acc[mf][nf][3] + q1.y + bb.y, 0.f);
                *reinterpret_cast<float2*>(p0) = o0;
                *reinterpret_cast<float2*>(p1) = o1;
            } else {
                *reinterpret_cast<float2*>(p0) = make_float2(acc[mf][nf][0], acc[mf][nf][1]);
                *reinterpret_cast<float2*>(p1) = make_float2(acc[mf][nf][2], acc[mf][nf][3]);
            }
        }
    }
}

// ---------------------------------------------------------------------------
// Kernel 1 (k_main): weight prep + passthrough pack + GEMM part-2 (overlapped)
// + mean stream. Low-reg gemm path (PIPE=false) to keep 2-CTA residency.
// ---------------------------------------------------------------------------
__global__ void __launch_bounds__(256) k_main(
    const float* __restrict__ itex, const float* __restrict__ iimg,
    const float* __restrict__ btxt, const float* __restrict__ bimg,
    const float* __restrict__ Wri,  const float* __restrict__ Wrt,
    const float* __restrict__ Wu,   const float* __restrict__ bu,
    const float* __restrict__ bli,  const float* __restrict__ blt,
    const float* __restrict__ Wli,  const float* __restrict__ Wlt,
    float* __restrict__ out)
{
    __shared__ __align__(1024) unsigned char smu[49152];

    const int bx  = blockIdx.x;
    const int tid = threadIdx.x;

    if (bx < N1_WCOMB) {
        // ---- W_comb tile -> bf16 hi/lo into g_W cols [1024,2048) ----
        float (*As)[68] = reinterpret_cast<float(*)[68]>(smu);
        float (*Bs)[64] = reinterpret_cast<float(*)[64]>(smu + 16384);

        const int n0 = (bx & 15) * 64;
        const int m0 = (bx >> 4) * 64;
        const int tx = tid & 15, ty = tid >> 4;
        const int arow = tid >> 2, ac = (tid & 3) * 4;
        const int brow = tid >> 4, bc = (tid & 15) * 4;

        float acc[4][4] = {};
        float4 ra, rb;
        {
            float4 x = *reinterpret_cast<const float4*>(Wri + (m0 + arow) * 512 + ac);
            float4 y = *reinterpret_cast<const float4*>(Wrt + (m0 + arow) * 512 + ac);
            ra = make_float4(x.x + y.x, x.y + y.y, x.z + y.z, x.w + y.w);
            rb = *reinterpret_cast<const float4*>(Wu + brow * 1024 + n0 + bc);
        }
        for (int kt = 0; kt < 32; ++kt) {
            As[ac + 0][arow] = ra.x; As[ac + 1][arow] = ra.y;
            As[ac + 2][arow] = ra.z; As[ac + 3][arow] = ra.w;
            *reinterpret_cast<float4*>(&Bs[brow][bc]) = rb;
            __syncthreads();
            if (kt < 31) {
                const int h0 = (kt + 1) * 16;
                float4 x = *reinterpret_cast<const float4*>(Wri + (m0 + arow) * 512 + h0 + ac);
                float4 y = *reinterpret_cast<const float4*>(Wrt + (m0 + arow) * 512 + h0 + ac);
                ra = make_float4(x.x + y.x, x.y + y.y, x.z + y.z, x.w + y.w);
                rb = *reinterpret_cast<const float4*>(Wu + (h0 + brow) * 1024 + n0 + bc);
            }
            #pragma unroll
            for (int kk = 0; kk < 16; ++kk) {
                float4 a = *reinterpret_cast<const float4*>(&As[kk][ty * 4]);
                float4 b = *reinterpret_cast<const float4*>(&Bs[kk][tx * 4]);
                acc[0][0] += a.x*b.x; acc[0][1] += a.x*b.y; acc[0][2] += a.x*b.z; acc[0][3] += a.x*b.w;
                acc[1][0] += a.y*b.x; acc[1][1] += a.y*b.y; acc[1][2] += a.y*b.z; acc[1][3] += a.y*b.w;
                acc[2][0] += a.z*b.x; acc[2][1] += a.z*b.y; acc[2][2] += a.z*b.z; acc[2][3] += a.z*b.w;
                acc[3][0] += a.w*b.x; acc[3][1] += a.w*b.y; acc[3][2] += a.w*b.z; acc[3][3] += a.w*b.w;
            }
            __syncthreads();
        }
        #pragma unroll
        for (int rr = 0; rr < 4; ++rr) {
            float4 o = make_float4(acc[rr][0], acc[rr][1], acc[rr][2], acc[rr][3]);
            split_store4(g_Whi, g_Wlo,
                         (size_t)(m0 + ty * 4 + rr) * KX + 1024 + n0 + tx * 4, o);
        }
        publish(&g_c_wcomb);
        return;
    }

    if (bx < N1_WCOMB + N1_PASS) {
        // ---- passthrough pack: X cols [1024,2048) from it/ii, 64 rows/CTA ----
        const int j = bx - N1_WCOMB;
        #pragma unroll 4
        for (int q = 0; q < 64; ++q) {
            const int id = q * 256 + tid;
            const int r  = id >> 8;
            const int ci = id & 255;
            const int b  = j * 64 + r;
            float4 v;
            int xcol;
            if (ci < 128) { v = reinterpret_cast<const float4*>(itex + (size_t)b * DIM)[ci];
                            xcol = 1024 + ci * 4; }
            else          { v = reinterpret_cast<const float4*>(iimg + (size_t)b * DIM)[ci - 128];
                            xcol = 1536 + (ci - 128) * 4; }
            split_store4(g_Xhi, g_Xlo, (size_t)b * KX + xcol, v);
        }
        publish(&g_c_pass);
        return;
    }

    if (bx < N1_WCOMB + N1_PASS + N1_BCOMB) {
        // ---- b_comb ----
        float* bs = reinterpret_cast<float*>(smu);
        bs[tid] = bu[tid];
        bs[tid + 256] = bu[tid + 256];
        __syncthreads();
        const int n = (bx - N1_WCOMB - N1_PASS) * 256 + tid;
        const float4* p1 = reinterpret_cast<const float4*>(Wri + n * 512);
        const float4* p2 = reinterpret_cast<const float4*>(Wrt + n * 512);
        float acc = 0.f;
        #pragma unroll 4
        for (int h4 = 0; h4 < 128; ++h4) {
            float4 a = p1[h4], b = p2[h4];
            const float* bb = bs + h4 * 4;
            acc += (a.x + b.x) * bb[0] + (a.y + b.y) * bb[1]
                 + (a.z + b.z) * bb[2] + (a.w + b.w) * bb[3];
        }
        g_bcomb[n] = acc + bli[n] + blt[n];
        return;
    }

    if (bx < N1_WCOMB + N1_PASS + N1_BCOMB + N1_WPACK) {
        // ---- pack [Wli | Wlt] -> g_W cols [0,1024) ----
        const int base = (bx - N1_WCOMB - N1_PASS - N1_BCOMB) * 256 * 8;
        #pragma unroll
        for (int it = 0; it < 8; ++it) {
            const int id = base + it * 256 + tid;
            const int n  = id >> 8;
            const int k  = (id & 255) * 4;
            float4 v;
            if (k < 512) v = *reinterpret_cast<const float4*>(Wli + n * 512 + k);
            else         v = *reinterpret_cast<const float4*>(Wlt + n * 512 + (k - 512));
            split_store4(g_Whi, g_Wlo, (size_t)n * KX + k, v);
        }
        return;
    }

    if (bx < N1_WCOMB + N1_PASS + N1_BCOMB + N1_WPACK + N1_P2) {
        // ---- GEMM part-2: K [1024,2048), overlapped with the mean stream ----
        if (tid == 0) {
            wait_ge(&g_c_wcomb, N1_WCOMB);
            wait_ge(&g_c_pass,  N1_PASS);
        }
        __syncthreads();
        const int id = bx - (N1_WCOMB + N1_PASS + N1_BCOMB + N1_WPACK);
        const int n0 = (id & 7) * 64;
        const int m0 = (id >> 3) * 128;
        gemm_tile<false>(out, smu, m0, n0, 1024, false);
        return;
    }

    // ---- mean stream: 4 contiguous batch rows per CTA, cols [0,1024) ----
    {
        const int widx = bx - (N1_WCOMB + N1_PASS + N1_BCOMB + N1_WPACK + N1_P2);
        const bool lo  = (tid < 128);
        const int chunk = lo ? tid : (tid - 128);
        const int xoff  = lo ? 0 : 512;
        const float* srcM = lo ? bimg : btxt;
        const float s = 1.0f / (float)NODES;

        #pragma unroll 1
        for (int r = 0; r < 4; ++r) {
            const int b = widx * 4 + r;
            const float4* p = reinterpret_cast<const float4*>(
                                  srcM + (size_t)b * NODES * DIM) + chunk;
            float4 acc = make_float4(0.f, 0.f, 0.f, 0.f);
            #pragma unroll 16
            for (int m = 0; m < NODES; ++m) {
                float4 v = __ldcs(p + (size_t)m * (DIM / 4));
                acc.x += v.x; acc.y += v.y; acc.z += v.z; acc.w += v.w;
            }
            acc.x *= s; acc.y *= s; acc.z *= s; acc.w *= s;
            split_store4(g_Xhi, g_Xlo, (size_t)b * KX + xoff + chunk * 4, acc);
        }
    }
}

// ---------------------------------------------------------------------------
// Kernel 2 (k_tail): GEMM part-1 (K [0,1024)) + finalize, ldsm-pipelined
// (PIPE=true). Last CTA self-resets sync flags for the next graph replay.
// ---------------------------------------------------------------------------
__global__ void __launch_bounds__(256) k_tail(float* __restrict__ out)
{
    __shared__ __align__(1024) unsigned char smu[49152];
    const int n0 = blockIdx.x * 64;
    const int m0 = blockIdx.y * 128;
    gemm_tile<true>(out, smu, m0, n0, 0, true);

    __syncthreads();
    if (threadIdx.x == 0) {
        const uint32_t old = atomicAdd(&g_done, 1u);
        if (old == (uint32_t)(N_TAIL - 1)) {
            g_c_wcomb = 0;
            g_c_pass  = 0;
            g_done    = 0;
            __threadfence();
        }
    }
}

// ---------------------------------------------------------------------------
extern "C" void kernel_launch(void* const* d_in, const int* in_sizes, int n_in,
                              void* d_out, int out_size)
{
    const float* input_text = (const float*)d_in[0];
    const float* input_img  = (const float*)d_in[1];
    const float* btxt       = (const float*)d_in[2];
    const float* bimg       = (const float*)d_in[3];
    const float* W_user     = (const float*)d_in[4];
    const float* b_user     = (const float*)d_in[5];
    const float* W_l_img    = (const float*)d_in[6];
    const float* b_l_img    = (const float*)d_in[7];
    const float* W_r_img    = (const float*)d_in[8];
    const float* W_l_txt    = (const float*)d_in[9];
    const float* b_l_txt    = (const float*)d_in[10];
    const float* W_r_txt    = (const float*)d_in[11];
    float* out = (float*)d_out;

    k_main<<<GRID1, 256>>>(input_text, input_img, btxt, bimg,
                           W_r_img, W_r_txt, W_user, b_user, b_l_img, b_l_txt,
                           W_l_img, W_l_txt, out);
    k_tail<<<dim3(8, 16), 256>>>(out);
}